// round 16
// baseline (speedup 1.0000x reference)
#include <cuda_runtime.h>
#include <cuda_fp16.h>
#include <math.h>
#include <stdint.h>

#define H 2048
#define NOPS 8
#define NNODES 7
#define NB 148          // persistent blocks; <= SM count (148 B300 / 152 GB300)
#define NT 896          // 28 warps per block: 2 warps per output element
#define WPB 14          // output elements per block; NB*WPB = 2072 >= H
#define GSTRIDE ((size_t)H * H)   // stride between gate rows of one output elem
#define PD 5            // cp.async pipeline depth (1KB chunks per slot)

// ---------------- device state (no allocations allowed) ----------------
__device__ float g_c[2][H];
__device__ float g_h0[2][H];          // layer-0 h ping-pong
__device__ float g_h1[2][H];          // layer-1 h ping-pong
__device__ float g_anchors[NNODES + 2][H];     // [0],[1] stay zero
__device__ float g_anchors_w1[NNODES + 2][H];
__device__ float g_hw[H];
// g_pre slots: 0..8  = Wih0 @ w_emb[k];  9..14 = Wih0 @ anchors[k] (slot 7+k)
__device__ float g_pre[16][4][H];
__device__ float g_bsum[2][4][H];              // b_ih + b_hh per layer/gate

// fp16 staged weights
__device__ __half g_wih_h[2 * 4 * H * H];
__device__ __half g_whh_h[2 * 4 * H * H];
__device__ __half g_emba_h[H * H];
__device__ __half g_hida_h[H * H];

// software grid barrier (sense-reversing)
__device__ unsigned g_bar_arrive;
__device__ volatile unsigned g_bar_gen;

__device__ __forceinline__ void grid_sync() {
    __threadfence();
    __syncthreads();
    if (threadIdx.x == 0) {
        unsigned gen = g_bar_gen;
        if (atomicAdd(&g_bar_arrive, 1u) == NB - 1) {
            g_bar_arrive = 0;
            __threadfence();
            g_bar_gen = gen + 1;
        } else {
            while (g_bar_gen == gen) __nanosleep(32);
            __threadfence();
        }
    }
    __syncthreads();
}

// ---------------- helpers ----------------
__device__ __forceinline__ float warp_reduce(float v) {
#pragma unroll
    for (int o = 16; o > 0; o >>= 1) v += __shfl_down_sync(0xffffffffu, v, o);
    return v;
}

__device__ __forceinline__ float sigf(float x) { return 1.0f / (1.0f + expf(-x)); }

__device__ __forceinline__ float dot8(uint4 q, float4 e, float4 o) {
    const __half2* hh = (const __half2*)&q;
    float2 f0 = __half22float2(hh[0]);
    float2 f1 = __half22float2(hh[1]);
    float2 f2 = __half22float2(hh[2]);
    float2 f3 = __half22float2(hh[3]);
    float acc = f0.x * e.x + f0.y * e.y;
    acc += f1.x * e.z + f1.y * e.w;
    acc += f2.x * o.x + f2.y * o.y;
    acc += f3.x * o.z + f3.y * o.w;
    return acc;
}

// full 4KB row dot vs smem E/O vectors (register front-batch; small phases)
__device__ __forceinline__ float dotrow(const uint4* __restrict__ row,
                                        const float4* __restrict__ E,
                                        const float4* __restrict__ O, int lane) {
    uint4 q[8];
#pragma unroll
    for (int i = 0; i < 8; i++) q[i] = __ldcg(row + i * 32 + lane);
    float acc = 0.0f;
#pragma unroll
    for (int i = 0; i < 8; i++) {
        int m = i * 32 + lane;
        acc += dot8(q[i], E[m], O[m]);
    }
    return acc;
}

// ---------------- deep cp.async pipeline: 1KB chunks, PD slots/warp ----------
// Chunk ci covers row (ci>>2), uint4 indices [(ci&3)*64, (ci&3)*64+64).
// Consume order (ci ascending, c ascending) == dotrow's i=0..7 order exactly.
__device__ __forceinline__ void pf_chunk(const __half* base0, int ci,
                                         int lane, uint4* slot) {
    const uint4* src = (const uint4*)(base0 + (size_t)(ci >> 2) * GSTRIDE)
                     + (ci & 3) * 64;
#pragma unroll
    for (int c = 0; c < 2; c++) {
        uint32_t sa = (uint32_t)__cvta_generic_to_shared(slot + c * 32 + lane);
        asm volatile("cp.async.cg.shared.global [%0], [%1], 16;"
                     :: "r"(sa), "l"(src + c * 32 + lane) : "memory");
    }
    asm volatile("cp.async.commit_group;" ::: "memory");
}

__device__ __forceinline__ void cp_wait(int pend) {
    if (pend <= 0)      asm volatile("cp.async.wait_group 0;" ::: "memory");
    else if (pend == 1) asm volatile("cp.async.wait_group 1;" ::: "memory");
    else if (pend == 2) asm volatile("cp.async.wait_group 2;" ::: "memory");
    else if (pend == 3) asm volatile("cp.async.wait_group 3;" ::: "memory");
    else                asm volatile("cp.async.wait_group 4;" ::: "memory");
}

// Prime the pipeline (issue first min(PD, nr*4) chunks). Returns P.
__device__ __forceinline__ int pipe_prime(const __half* base0, int nr,
                                          int lane, uint4* wb) {
    int total = nr * 4;
    int P = 0;
    for (; P < total && P < PD; P++)
        pf_chunk(base0, P, lane, wb + (P % PD) * 64);
    return P;
}

// Consume all chunks, refilling as we go; out[r] accumulates row r's partial.
__device__ __forceinline__ void pipe_run(const __half* base0, int nr, int P,
                                         const float4* __restrict__ E,
                                         const float4* __restrict__ O,
                                         float* out, int lane, uint4* wb) {
    int total = nr * 4;
    for (int C = 0; C < total; C++) {
        cp_wait(P - C - 1);
        const uint4* b = wb + (C % PD) * 64;
        int j = C & 3;
        float a = 0.0f;
#pragma unroll
        for (int c = 0; c < 2; c++) {
            uint4 q = b[c * 32 + lane];
            int m = j * 64 + c * 32 + lane;
            a += dot8(q, E[m], O[m]);
        }
        out[C >> 2] += a;
        if (P < total) { pf_chunk(base0, P, lane, wb + (P % PD) * 64); P++; }
    }
}

// ---------------- threefry2x32 (exact JAX semantics) ----------------
__device__ __forceinline__ void threefry2x32(uint32_t k0, uint32_t k1,
                                             uint32_t x0, uint32_t x1,
                                             uint32_t& o0, uint32_t& o1) {
    uint32_t ks0 = k0, ks1 = k1, ks2 = k0 ^ k1 ^ 0x1BD11BDAu;
    x0 += ks0; x1 += ks1;
#define TF_ROUND(r) { x0 += x1; x1 = (x1 << (r)) | (x1 >> (32 - (r))); x1 ^= x0; }
    TF_ROUND(13) TF_ROUND(15) TF_ROUND(26) TF_ROUND(6)
    x0 += ks1; x1 += ks2 + 1u;
    TF_ROUND(17) TF_ROUND(29) TF_ROUND(16) TF_ROUND(24)
    x0 += ks2; x1 += ks0 + 2u;
    TF_ROUND(13) TF_ROUND(15) TF_ROUND(26) TF_ROUND(6)
    x0 += ks0; x1 += ks1 + 3u;
    TF_ROUND(17) TF_ROUND(29) TF_ROUND(16) TF_ROUND(24)
    x0 += ks1; x1 += ks2 + 4u;
    TF_ROUND(13) TF_ROUND(15) TF_ROUND(26) TF_ROUND(6)
    x0 += ks2; x1 += ks0 + 5u;
#undef TF_ROUND
    o0 = x0; o1 = x1;
}

__device__ __forceinline__ float gumbel_from_bits(uint32_t b) {
    float f = __uint_as_float((b >> 9) | 0x3f800000u) - 1.0f;
    float u = f + 1.17549435e-38f;
    return -logf(-logf(u));
}

// Warp-parallel exact-JAX sampling (partitionable threefry). Redundant per block.
__device__ int sample_warp(float lv, int n, int t, int slot,
                           float* s_stats, int* s_arc) {
    int lane = threadIdx.x & 31;
    const unsigned mask = 0xffffffffu;
    float m = lv;
#pragma unroll
    for (int o = 16; o; o >>= 1) m = fmaxf(m, __shfl_xor_sync(mask, m, o));
    float sh = lv - m;
    float e = (lane < n) ? expf(sh) : 0.0f;
    float se = e;
#pragma unroll
    for (int o = 16; o; o >>= 1) se += __shfl_xor_sync(mask, se, o);
    float lse = logf(se);
    float lpv = sh - lse;
    float ent = (lane < n) ? lpv * expf(lpv) : 0.0f;
#pragma unroll
    for (int o = 16; o; o >>= 1) ent += __shfl_xor_sync(mask, ent, o);

    uint32_t k0, k1;
    threefry2x32(0u, 42u, 0u, (uint32_t)t, k0, k1);
    float z = -1e30f;
    if (lane < n) {
        uint32_t o0, o1;
        threefry2x32(k0, k1, 0u, (uint32_t)lane, o0, o1);
        z = lv + gumbel_from_bits(o0 ^ o1);
    }
    float bz = z;
    int bi = (lane < n) ? lane : (1 << 30);
#pragma unroll
    for (int o = 16; o; o >>= 1) {
        float oz = __shfl_xor_sync(mask, bz, o);
        int oi = __shfl_xor_sync(mask, bi, o);
        if (oz > bz || (oz == bz && oi < bi)) { bz = oz; bi = oi; }
    }
    float lpsel = __shfl_sync(mask, lpv, bi);
    if (lane == 0) {
        s_stats[0] += lpsel;
        s_stats[1] -= ent;
        s_arc[slot] = bi;
    }
    return bi;
}

// ---------------- fp32 -> fp16 conversion (R11-proven) ----------------
__device__ __forceinline__ uint4 pack_half8(float4 a0, float4 a1) {
    __half2 h0 = __floats2half2_rn(a0.x, a0.y);
    __half2 h1 = __floats2half2_rn(a0.z, a0.w);
    __half2 h2 = __floats2half2_rn(a1.x, a1.y);
    __half2 h3 = __floats2half2_rn(a1.z, a1.w);
    uint4 q;
    q.x = *reinterpret_cast<uint32_t*>(&h0);
    q.y = *reinterpret_cast<uint32_t*>(&h1);
    q.z = *reinterpret_cast<uint32_t*>(&h2);
    q.w = *reinterpret_cast<uint32_t*>(&h3);
    return q;
}

__device__ void conv_arr(const float* __restrict__ src, __half* __restrict__ dst, int n8) {
    int i = blockIdx.x * NT + threadIdx.x;
    const int stride = NB * NT;
    const float4* s4 = (const float4*)src;
    uint4* d4 = (uint4*)dst;
    for (; i + 3 * stride < n8; i += 4 * stride) {
        float4 a[8];
#pragma unroll
        for (int k = 0; k < 4; k++) {
            a[2 * k]     = __ldlu(s4 + 2 * (size_t)(i + k * stride));
            a[2 * k + 1] = __ldlu(s4 + 2 * (size_t)(i + k * stride) + 1);
        }
#pragma unroll
        for (int k = 0; k < 4; k++)
            d4[i + k * stride] = pack_half8(a[2 * k], a[2 * k + 1]);
    }
    for (; i < n8; i += stride) {
        float4 a0 = __ldlu(s4 + 2 * (size_t)i);
        float4 a1 = __ldlu(s4 + 2 * (size_t)i + 1);
        d4[i] = pack_half8(a0, a1);
    }
}

// ---------------- precompute: g_pre[k][g][gw] = dot(Wih0[g*H+gw,:], w_emb[k,:]) ----
// Split across the warp pair: A-warp gates {0,1}, B-warp gates {2,3}.
__device__ void precompute_phase(const __half* __restrict__ Wih0,
                                 const float* __restrict__ w_emb) {
    int tid = threadIdx.x, w = tid >> 5, lane = tid & 31;
    bool isA = (w < WPB);
    int elem = isA ? w : (w - WPB);
    int gw = blockIdx.x * WPB + elem;
    if (gw >= H) return;
    int gbase = isA ? 0 : 2;
#pragma unroll
    for (int k2 = 0; k2 < 2; k2++) {
        int g = gbase + k2;
        const uint4* rp = (const uint4*)(Wih0 + ((size_t)g * H + gw) * H);
        uint4 q[8];
#pragma unroll
        for (int i = 0; i < 8; i++) q[i] = __ldcg(rp + i * 32 + lane);
        float a9[NOPS + 1];
#pragma unroll
        for (int k = 0; k <= NOPS; k++) a9[k] = 0.0f;
#pragma unroll
        for (int i = 0; i < 8; i++) {
            int m = i * 32 + lane;
#pragma unroll
            for (int k = 0; k <= NOPS; k++) {
                const float4* wr = (const float4*)(w_emb + (size_t)k * H);
                a9[k] += dot8(q[i], __ldg(wr + 2 * m), __ldg(wr + 2 * m + 1));
            }
        }
#pragma unroll
        for (int k = 0; k <= NOPS; k++) {
            float r = warp_reduce(a9[k]);
            if (lane == 0) g_pre[k][g][gw] = r;
        }
    }
}

// ---------------- LSTM layer phase: 2 warps/elem + deep cp.async pipeline ----
// xk: -1 dense x (use xp), -2 zero x, >=0 pre-table index (skip Wih load).
// hz: h_prev is all-zero -> skip Whh load entirely.
// prek >= 2: A-warp computes Wih0 @ g_anchors[prek] -> pre slot 7+prek.
__device__ void lstm_phase(const __half* __restrict__ Wih,
                           const __half* __restrict__ Whh,
                           const float* __restrict__ bsum,   // [4][H]
                           int xk, const float* __restrict__ xp,
                           bool hz, int prek,
                           const float* __restrict__ hprev,
                           float* __restrict__ cvec,
                           float* __restrict__ hout,
                           float* __restrict__ anchor_dst,
                           float4* sEx, float4* sOx, float4* sEh, float4* sOh,
                           float (*sA)[4], float (*sB)[4], uint4* wbuf) {
    int tid = threadIdx.x, w = tid >> 5, lane = tid & 31;
    bool isA = (w < WPB);
    int elem = isA ? w : (w - WPB);
    int gw = blockIdx.x * WPB + elem;
    bool valid = (gw < H);
    uint4* wb = wbuf + w * (PD * 64);

    // decide this warp's row set: base pointer (first row of the set) + count
    const __half* base0 = nullptr;
    int nr = 0;
    bool preMode = false, useX = false;   // useX: consume against sEx/sOx
    if (valid) {
        if (isA) {
            if (xk == -1)      { base0 = Wih + (size_t)gw * H; nr = 4; useX = true; }
            else if (prek >= 2){ base0 = Wih + (size_t)gw * H; nr = 4; useX = true; preMode = true; }
            else if (!hz)      { base0 = Whh + (size_t)gw * H; nr = 2; }          // gates 0,1
        } else {
            if (!hz) {
                if (xk == -1 || prek >= 2) { base0 = Whh + (size_t)gw * H; nr = 4; }
                else { base0 = Whh + ((size_t)2 * H + gw) * H; nr = 2; }          // gates 2,3
            }
        }
    }

    // prime the weight pipeline BEFORE staging (overlaps first latency)
    int P = (valid && nr > 0) ? pipe_prime(base0, nr, lane, wb) : 0;

    // stage activations into shared E/O buffers
    if (xk == -1) {
        const float4* x4 = (const float4*)xp;
        for (int i = tid; i < 256; i += NT) {
            sEx[i] = __ldcg(x4 + 2 * i);
            sOx[i] = __ldcg(x4 + 2 * i + 1);
        }
    } else if (prek >= 2) {
        const float4* a4 = (const float4*)g_anchors[prek];
        for (int i = tid; i < 256; i += NT) {
            sEx[i] = __ldcg(a4 + 2 * i);
            sOx[i] = __ldcg(a4 + 2 * i + 1);
        }
    }
    if (!hz) {
        const float4* h4 = (const float4*)hprev;
        for (int i = tid; i < 256; i += NT) {
            sEh[i] = __ldcg(h4 + 2 * i);
            sOh[i] = __ldcg(h4 + 2 * i + 1);
        }
    }
    __syncthreads();

    if (valid) {
        float out[4] = {0.0f, 0.0f, 0.0f, 0.0f};
        if (nr > 0) {
            const float4* E = useX ? sEx : sEh;
            const float4* O = useX ? sOx : sOh;
            pipe_run(base0, nr, P, E, O, out, lane, wb);
        }
        float r[4] = {0.0f, 0.0f, 0.0f, 0.0f};
        if (preMode) {
#pragma unroll
            for (int g = 0; g < 4; g++) {
                float a = warp_reduce(out[g]);
                if (lane == 0) g_pre[7 + prek][g][gw] = a;
            }
        } else if (nr == 4) {
            r[0] = out[0]; r[1] = out[1]; r[2] = out[2]; r[3] = out[3];
        } else if (nr == 2) {
            if (isA) { r[0] = out[0]; r[1] = out[1]; }
            else     { r[2] = out[0]; r[3] = out[1]; }
        }
#pragma unroll
        for (int g = 0; g < 4; g++) r[g] = warp_reduce(r[g]);
        if (lane == 0) {
            float (*dst)[4] = isA ? sA : sB;
            dst[elem][0] = r[0]; dst[elem][1] = r[1];
            dst[elem][2] = r[2]; dst[elem][3] = r[3];
        }
    }
    __syncthreads();

    if (valid && isA && lane == 0) {
        float g4[4];
#pragma unroll
        for (int g = 0; g < 4; g++)
            g4[g] = sA[elem][g] + sB[elem][g]
                  + (xk >= 0 ? __ldcg(&g_pre[xk][g][gw]) : 0.0f)
                  + bsum[g * H + gw];
        float c2 = sigf(g4[1]) * cvec[gw] + sigf(g4[0]) * tanhf(g4[2]);
        float h2 = sigf(g4[3]) * tanhf(c2);
        cvec[gw] = c2;
        hout[gw] = h2;
        if (anchor_dst) anchor_dst[gw] = h2;
    }
}

// ---------------- matvec phase: dst[gw] = dot(M[gw,:], v); split row halves ----
__device__ void matvec_phase(const __half* __restrict__ M,
                             const float* __restrict__ v,
                             float* __restrict__ dst,
                             float4* sEh, float4* sOh,
                             float (*sA)[4], float (*sB)[4]) {
    int tid = threadIdx.x, w = tid >> 5, lane = tid & 31;
    bool isA = (w < WPB);
    int elem = isA ? w : (w - WPB);
    int gw = blockIdx.x * WPB + elem;
    bool valid = (gw < H);

    const float4* h4 = (const float4*)v;
    for (int i = tid; i < 256; i += NT) {
        sEh[i] = __ldcg(h4 + 2 * i);
        sOh[i] = __ldcg(h4 + 2 * i + 1);
    }
    __syncthreads();

    if (valid) {
        const uint4* row = (const uint4*)(M + (size_t)gw * H);
        int off = isA ? 0 : 4;
        uint4 q[4];
#pragma unroll
        for (int i = 0; i < 4; i++) q[i] = __ldcg(row + (off + i) * 32 + lane);
        float acc = 0.0f;
#pragma unroll
        for (int i = 0; i < 4; i++) {
            int m = (off + i) * 32 + lane;
            acc += dot8(q[i], sEh[m], sOh[m]);
        }
        acc = warp_reduce(acc);
        if (lane == 0) (isA ? sA : sB)[elem][0] = acc;
    }
    __syncthreads();
    if (valid && isA && lane == 0) dst[gw] = sA[elem][0] + sB[elem][0];
}

// ---------------- sampling (R7-proven, redundant across ALL blocks) ----------
__device__ int node_sample(const float* __restrict__ v_attn, int n, int t, int slot,
                           float* s_log, int* s_sel, float* s_stats, int* s_arc) {
    int tid = threadIdx.x, w = tid >> 5, lane = tid & 31;
    if (w < n) {
        const float4* aw = (const float4*)g_anchors_w1[w];
        const float4* hw4 = (const float4*)g_hw;
        const float4* va = (const float4*)v_attn;
        float acc = 0.0f;
#pragma unroll 4
        for (int i = lane; i < H / 4; i += 32) {
            float4 a = __ldcg(aw + i), b = __ldcg(hw4 + i), c = __ldg(va + i);
            acc += c.x * tanhf(a.x + b.x) + c.y * tanhf(a.y + b.y)
                 + c.z * tanhf(a.z + b.z) + c.w * tanhf(a.w + b.w);
        }
        acc = warp_reduce(acc);
        if (lane == 0) s_log[w] = acc;
    }
    __syncthreads();
    if (w == 0) {
        float lv = (lane < n) ? 2.5f * tanhf(s_log[lane] / 5.0f) : -1e30f;
        int bi = sample_warp(lv, n, t, slot, s_stats, s_arc);
        if (lane == 0) *s_sel = bi;
    }
    __syncthreads();
    return *s_sel;
}

__device__ int op_sample(const float* __restrict__ w_soft_w,
                         const float* __restrict__ w_soft_b,
                         const float* __restrict__ h1,
                         int t, int slot,
                         float* s_log, int* s_sel, float* s_stats, int* s_arc) {
    int tid = threadIdx.x, w = tid >> 5, lane = tid & 31;
    if (w < NOPS) {
        const float4* row = (const float4*)(w_soft_w + (size_t)w * H);
        const float4* h4 = (const float4*)h1;
        float acc = 0.0f;
#pragma unroll 4
        for (int i = lane; i < H / 4; i += 32) {
            float4 a = __ldg(row + i), b = __ldcg(h4 + i);
            acc += a.x * b.x + a.y * b.y + a.z * b.z + a.w * b.w;
        }
        acc = warp_reduce(acc);
        if (lane == 0) s_log[w] = acc + __ldg(w_soft_b + w);
    }
    __syncthreads();
    if (w == 0) {
        float lv = (lane < NOPS) ? tanhf(s_log[lane] / 5.0f) : -1e30f;  // TANH_C/OP_TANH_RED = 1
        int bi = sample_warp(lv, NOPS, t, slot, s_stats, s_arc);
        if (lane == 0) *s_sel = bi;
    }
    __syncthreads();
    return *s_sel;
}

// ---------------- the persistent kernel ----------------
__global__ void __launch_bounds__(NT, 1) controller_kernel(
    const float* __restrict__ w_emb, const float* __restrict__ emb_attn,
    const float* __restrict__ hid_attn, const float* __restrict__ v_attn,
    const float* __restrict__ w_soft_w, const float* __restrict__ w_soft_b,
    const float* __restrict__ w_ih, const float* __restrict__ w_hh,
    const float* __restrict__ b_ih, const float* __restrict__ b_hh,
    float* __restrict__ out) {
    extern __shared__ uint4 wbuf[];    // 28 warps x PD x 1KB slots
    __shared__ float4 sEx[256], sOx[256], sEh[256], sOh[256];
    __shared__ float sA[WPB][4], sB[WPB][4];
    __shared__ float s_log[NOPS];
    __shared__ int s_sel;
    __shared__ float s_stats[2];
    __shared__ int s_arc[4 * NNODES];

    // phase 0: fp16 staging + state init + combined biases
    conv_arr(w_ih, g_wih_h, 2 * 4 * H * H / 8);
    conv_arr(w_hh, g_whh_h, 2 * 4 * H * H / 8);
    conv_arr(emb_attn, g_emba_h, H * H / 8);
    conv_arr(hid_attn, g_hida_h, H * H / 8);
    {
        int gid = blockIdx.x * NT + threadIdx.x;
        if (gid < (NNODES + 2) * H) ((float*)g_anchors)[gid] = 0.0f;
        if (gid < 2 * H) ((float*)g_c)[gid] = 0.0f;
        if (gid < 2 * H) ((float*)g_h0)[gid] = 0.0f;
        if (gid < 2 * H) ((float*)g_h1)[gid] = 0.0f;
        if (gid < 2 * 4 * H) ((float*)g_bsum)[gid] = b_ih[gid] + b_hh[gid];
        if (threadIdx.x == 0) { s_stats[0] = 0.0f; s_stats[1] = 0.0f; }
    }
    grid_sync();

    // phase 1: Wih0 @ all-9-embeddings precompute (warp-pair split)
    precompute_phase(g_wih_h, w_emb);
    grid_sync();

    const __half* Wih0 = g_wih_h;
    const __half* Wih1 = g_wih_h + (size_t)4 * H * H;
    const __half* Whh0 = g_whh_h;
    const __half* Whh1 = g_whh_h + (size_t)4 * H * H;
    const float* bs0 = &g_bsum[0][0][0];
    const float* bs1 = &g_bsum[1][0][0];

    int cur = 0;
    int xk = NOPS;                 // start input: g-embedding (w_emb row 8)
    int prek = -1;
    bool hz = true;                // step 1: all h/c are zero -> skip Whh loads

#define STEP(ANCH) do {                                                         \
    lstm_phase(Wih0, Whh0, bs0, xk, nullptr, hz, prek, g_h0[cur], g_c[0],       \
               g_h0[cur ^ 1], nullptr, sEx, sOx, sEh, sOh, sA, sB, wbuf);       \
    grid_sync();                                                                \
    lstm_phase(Wih1, Whh1, bs1, -1, g_h0[cur ^ 1], hz, -1, g_h1[cur],           \
               g_c[1], g_h1[cur ^ 1], (ANCH), sEx, sOx, sEh, sOh, sA, sB, wbuf);\
    grid_sync();                                                                \
    cur ^= 1; hz = false; prek = -1;                                            \
} while (0)

    // warm-up: two steps registering zero anchors + attn projections.
    STEP(nullptr);
    matvec_phase(g_emba_h, g_h1[cur], g_anchors_w1[0], sEh, sOh, sA, sB);
    __syncthreads();
    STEP(nullptr);
    matvec_phase(g_emba_h, g_h1[cur], g_anchors_w1[1], sEh, sOh, sA, sB);
    __syncthreads();

    int t = 0;
    for (int nid = 0; nid < NNODES; nid++) {
        // node-decision step 1 (x = g-emb lookup; also precompute the newest
        // anchor's Wih0 projection so node inputs become pure table lookups)
        if (nid >= 1) prek = nid + 1;
        STEP(nullptr);
        matvec_phase(g_hida_h, g_h1[cur], g_hw, sEh, sOh, sA, sB);
        grid_sync();
        int bi = node_sample(v_attn, nid + 2, t, 4 * nid, s_log, &s_sel, s_stats, s_arc);
        t++;
        xk = (bi < 2) ? -2 : (7 + bi);

        // node-decision step 2
        STEP(nullptr);
        matvec_phase(g_hida_h, g_h1[cur], g_hw, sEh, sOh, sA, sB);
        grid_sync();
        bi = node_sample(v_attn, nid + 2, t, 4 * nid + 2, s_log, &s_sel, s_stats, s_arc);
        t++;
        xk = (bi < 2) ? -2 : (7 + bi);

        // op step 1
        STEP(nullptr);
        int oi = op_sample(w_soft_w, w_soft_b, g_h1[cur], t, 4 * nid + 1,
                           s_log, &s_sel, s_stats, s_arc);
        t++;
        xk = oi;

        // op step 2
        STEP(nullptr);
        oi = op_sample(w_soft_w, w_soft_b, g_h1[cur], t, 4 * nid + 3,
                       s_log, &s_sel, s_stats, s_arc);
        t++;
        xk = oi;

        // anchor registration step (last node's anchor never affects outputs)
        if (nid < NNODES - 1) {
            STEP(g_anchors[nid + 2]);
            matvec_phase(g_emba_h, g_h1[cur], g_anchors_w1[nid + 2], sEh, sOh, sA, sB);
            __syncthreads();           // block-local; consumed >=2 barriers later
            xk = NOPS;
        }
    }
#undef STEP

    if (blockIdx.x == 0) {
        int i = threadIdx.x;
        if (i < 28) out[i] = (float)s_arc[i];
        if (i == 28) out[28] = s_stats[0];
        if (i == 29) out[29] = s_stats[1];
    }
}

// ---------------- host driver: ONE persistent kernel launch ----------------
extern "C" void kernel_launch(void* const* d_in, const int* in_sizes, int n_in,
                              void* d_out, int out_size) {
    const float* w_emb    = (const float*)d_in[0];
    const float* emb_attn = (const float*)d_in[1];
    const float* hid_attn = (const float*)d_in[2];
    const float* v_attn   = (const float*)d_in[3];
    const float* w_soft_w = (const float*)d_in[4];
    const float* w_soft_b = (const float*)d_in[5];
    const float* w_ih     = (const float*)d_in[6];
    const float* w_hh     = (const float*)d_in[7];
    const float* b_ih     = (const float*)d_in[8];
    const float* b_hh     = (const float*)d_in[9];

    const int WSMEM = 28 * PD * 64 * (int)sizeof(uint4);   // 143360 bytes
    cudaFuncSetAttribute(controller_kernel,
                         cudaFuncAttributeMaxDynamicSharedMemorySize, WSMEM);

    controller_kernel<<<NB, NT, WSMEM>>>(w_emb, emb_attn, hid_attn, v_attn,
                                         w_soft_w, w_soft_b, w_ih, w_hh,
                                         b_ih, b_hh, (float*)d_out);
}

// round 17
// speedup vs baseline: 1.3751x; 1.3751x over previous
#include <cuda_runtime.h>
#include <cuda_fp16.h>
#include <math.h>
#include <stdint.h>

#define H 2048
#define NOPS 8
#define NNODES 7
#define NB 148          // persistent blocks; <= SM count (148 B300 / 152 GB300)
#define NT 896          // 28 warps per block: 2 warps per output element
#define WPB 14          // output elements per block; NB*WPB = 2072 >= H

// ---------------- device state (no allocations allowed) ----------------
__device__ float g_c[2][H];
__device__ float g_h0[2][H];          // layer-0 h ping-pong
__device__ float g_h1[2][H];          // layer-1 h ping-pong
__device__ float g_anchors[NNODES + 2][H];     // [0],[1] stay zero
__device__ float g_anchors_w1[NNODES + 2][H];
__device__ float g_hw[H];
// g_pre slots: 0..8  = Wih0 @ w_emb[k];  9..14 = Wih0 @ anchors[k] (slot 7+k)
__device__ float g_pre[16][4][H];
__device__ float g_bsum[2][4][H];              // b_ih + b_hh per layer/gate

// fp16 staged weights
__device__ __half g_wih_h[2 * 4 * H * H];
__device__ __half g_whh_h[2 * 4 * H * H];
__device__ __half g_emba_h[H * H];
__device__ __half g_hida_h[H * H];

// software grid barrier (sense-reversing)
__device__ unsigned g_bar_arrive;
__device__ volatile unsigned g_bar_gen;

__device__ __forceinline__ void grid_sync() {
    __threadfence();
    __syncthreads();
    if (threadIdx.x == 0) {
        unsigned gen = g_bar_gen;
        if (atomicAdd(&g_bar_arrive, 1u) == NB - 1) {
            g_bar_arrive = 0;
            __threadfence();
            g_bar_gen = gen + 1;
        } else {
            while (g_bar_gen == gen) __nanosleep(32);
            __threadfence();
        }
    }
    __syncthreads();
}

// ---------------- helpers ----------------
__device__ __forceinline__ float warp_reduce(float v) {
#pragma unroll
    for (int o = 16; o > 0; o >>= 1) v += __shfl_down_sync(0xffffffffu, v, o);
    return v;
}

__device__ __forceinline__ float sigf(float x) { return 1.0f / (1.0f + expf(-x)); }

__device__ __forceinline__ float dot8(uint4 q, float4 e, float4 o) {
    const __half2* hh = (const __half2*)&q;
    float2 f0 = __half22float2(hh[0]);
    float2 f1 = __half22float2(hh[1]);
    float2 f2 = __half22float2(hh[2]);
    float2 f3 = __half22float2(hh[3]);
    float acc = f0.x * e.x + f0.y * e.y;
    acc += f1.x * e.z + f1.y * e.w;
    acc += f2.x * o.x + f2.y * o.y;
    acc += f3.x * o.z + f3.y * o.w;
    return acc;
}

// full 4KB row dot vs smem E/O vectors (front-batch 8 LDG.128, L2-cached)
__device__ __forceinline__ float dotrow(const uint4* __restrict__ row,
                                        const float4* __restrict__ E,
                                        const float4* __restrict__ O, int lane) {
    uint4 q[8];
#pragma unroll
    for (int i = 0; i < 8; i++) q[i] = __ldcg(row + i * 32 + lane);
    float acc = 0.0f;
#pragma unroll
    for (int i = 0; i < 8; i++) {
        int m = i * 32 + lane;
        acc += dot8(q[i], E[m], O[m]);
    }
    return acc;
}

// evict-first variant for Wih0-only streams: keeps the 117MB steady-state
// weight hot set (Wih1/Whh1/Whh0/attn) resident in L2.
__device__ __forceinline__ float dotrow_lu(const uint4* __restrict__ row,
                                           const float4* __restrict__ E,
                                           const float4* __restrict__ O, int lane) {
    uint4 q[8];
#pragma unroll
    for (int i = 0; i < 8; i++) q[i] = __ldlu(row + i * 32 + lane);
    float acc = 0.0f;
#pragma unroll
    for (int i = 0; i < 8; i++) {
        int m = i * 32 + lane;
        acc += dot8(q[i], E[m], O[m]);
    }
    return acc;
}

// ---------------- threefry2x32 (exact JAX semantics) ----------------
__device__ __forceinline__ void threefry2x32(uint32_t k0, uint32_t k1,
                                             uint32_t x0, uint32_t x1,
                                             uint32_t& o0, uint32_t& o1) {
    uint32_t ks0 = k0, ks1 = k1, ks2 = k0 ^ k1 ^ 0x1BD11BDAu;
    x0 += ks0; x1 += ks1;
#define TF_ROUND(r) { x0 += x1; x1 = (x1 << (r)) | (x1 >> (32 - (r))); x1 ^= x0; }
    TF_ROUND(13) TF_ROUND(15) TF_ROUND(26) TF_ROUND(6)
    x0 += ks1; x1 += ks2 + 1u;
    TF_ROUND(17) TF_ROUND(29) TF_ROUND(16) TF_ROUND(24)
    x0 += ks2; x1 += ks0 + 2u;
    TF_ROUND(13) TF_ROUND(15) TF_ROUND(26) TF_ROUND(6)
    x0 += ks0; x1 += ks1 + 3u;
    TF_ROUND(17) TF_ROUND(29) TF_ROUND(16) TF_ROUND(24)
    x0 += ks1; x1 += ks2 + 4u;
    TF_ROUND(13) TF_ROUND(15) TF_ROUND(26) TF_ROUND(6)
    x0 += ks2; x1 += ks0 + 5u;
#undef TF_ROUND
    o0 = x0; o1 = x1;
}

__device__ __forceinline__ float gumbel_from_bits(uint32_t b) {
    float f = __uint_as_float((b >> 9) | 0x3f800000u) - 1.0f;
    float u = f + 1.17549435e-38f;
    return -logf(-logf(u));
}

// Warp-parallel exact-JAX sampling (partitionable threefry). Redundant per block.
__device__ int sample_warp(float lv, int n, int t, int slot,
                           float* s_stats, int* s_arc) {
    int lane = threadIdx.x & 31;
    const unsigned mask = 0xffffffffu;
    float m = lv;
#pragma unroll
    for (int o = 16; o; o >>= 1) m = fmaxf(m, __shfl_xor_sync(mask, m, o));
    float sh = lv - m;
    float e = (lane < n) ? expf(sh) : 0.0f;
    float se = e;
#pragma unroll
    for (int o = 16; o; o >>= 1) se += __shfl_xor_sync(mask, se, o);
    float lse = logf(se);
    float lpv = sh - lse;
    float ent = (lane < n) ? lpv * expf(lpv) : 0.0f;
#pragma unroll
    for (int o = 16; o; o >>= 1) ent += __shfl_xor_sync(mask, ent, o);

    uint32_t k0, k1;
    threefry2x32(0u, 42u, 0u, (uint32_t)t, k0, k1);
    float z = -1e30f;
    if (lane < n) {
        uint32_t o0, o1;
        threefry2x32(k0, k1, 0u, (uint32_t)lane, o0, o1);
        z = lv + gumbel_from_bits(o0 ^ o1);
    }
    float bz = z;
    int bi = (lane < n) ? lane : (1 << 30);
#pragma unroll
    for (int o = 16; o; o >>= 1) {
        float oz = __shfl_xor_sync(mask, bz, o);
        int oi = __shfl_xor_sync(mask, bi, o);
        if (oz > bz || (oz == bz && oi < bi)) { bz = oz; bi = oi; }
    }
    float lpsel = __shfl_sync(mask, lpv, bi);
    if (lane == 0) {
        s_stats[0] += lpsel;
        s_stats[1] -= ent;
        s_arc[slot] = bi;
    }
    return bi;
}

// ---------------- fp32 -> fp16 conversion (R11-proven) ----------------
__device__ __forceinline__ uint4 pack_half8(float4 a0, float4 a1) {
    __half2 h0 = __floats2half2_rn(a0.x, a0.y);
    __half2 h1 = __floats2half2_rn(a0.z, a0.w);
    __half2 h2 = __floats2half2_rn(a1.x, a1.y);
    __half2 h3 = __floats2half2_rn(a1.z, a1.w);
    uint4 q;
    q.x = *reinterpret_cast<uint32_t*>(&h0);
    q.y = *reinterpret_cast<uint32_t*>(&h1);
    q.z = *reinterpret_cast<uint32_t*>(&h2);
    q.w = *reinterpret_cast<uint32_t*>(&h3);
    return q;
}

__device__ void conv_arr(const float* __restrict__ src, __half* __restrict__ dst, int n8) {
    int i = blockIdx.x * NT + threadIdx.x;
    const int stride = NB * NT;
    const float4* s4 = (const float4*)src;
    uint4* d4 = (uint4*)dst;
    for (; i + 3 * stride < n8; i += 4 * stride) {
        float4 a[8];
#pragma unroll
        for (int k = 0; k < 4; k++) {
            a[2 * k]     = __ldlu(s4 + 2 * (size_t)(i + k * stride));
            a[2 * k + 1] = __ldlu(s4 + 2 * (size_t)(i + k * stride) + 1);
        }
#pragma unroll
        for (int k = 0; k < 4; k++)
            d4[i + k * stride] = pack_half8(a[2 * k], a[2 * k + 1]);
    }
    for (; i < n8; i += stride) {
        float4 a0 = __ldlu(s4 + 2 * (size_t)i);
        float4 a1 = __ldlu(s4 + 2 * (size_t)i + 1);
        d4[i] = pack_half8(a0, a1);
    }
}

// ---------------- precompute: g_pre[k][g][gw] = dot(Wih0[g*H+gw,:], w_emb[k,:]) ----
// Split across the warp pair: A-warp gates {0,1}, B-warp gates {2,3}.
// Wih0 reads are evict-first (__ldlu): single-use stream, keep L2 clean.
__device__ void precompute_phase(const __half* __restrict__ Wih0,
                                 const float* __restrict__ w_emb) {
    int tid = threadIdx.x, w = tid >> 5, lane = tid & 31;
    bool isA = (w < WPB);
    int elem = isA ? w : (w - WPB);
    int gw = blockIdx.x * WPB + elem;
    if (gw >= H) return;
    int gbase = isA ? 0 : 2;
#pragma unroll
    for (int k2 = 0; k2 < 2; k2++) {
        int g = gbase + k2;
        const uint4* rp = (const uint4*)(Wih0 + ((size_t)g * H + gw) * H);
        uint4 q[8];
#pragma unroll
        for (int i = 0; i < 8; i++) q[i] = __ldlu(rp + i * 32 + lane);
        float a9[NOPS + 1];
#pragma unroll
        for (int k = 0; k <= NOPS; k++) a9[k] = 0.0f;
#pragma unroll
        for (int i = 0; i < 8; i++) {
            int m = i * 32 + lane;
#pragma unroll
            for (int k = 0; k <= NOPS; k++) {
                const float4* wr = (const float4*)(w_emb + (size_t)k * H);
                a9[k] += dot8(q[i], __ldg(wr + 2 * m), __ldg(wr + 2 * m + 1));
            }
        }
#pragma unroll
        for (int k = 0; k <= NOPS; k++) {
            float r = warp_reduce(a9[k]);
            if (lane == 0) g_pre[k][g][gw] = r;
        }
    }
}

// ---------------- LSTM layer phase: 2 warps per output element (R14-proven) ----
// xk: -1 dense x (use xp), -2 zero x, >=0 pre-table index (skip Wih load).
// hz: h_prev is all-zero -> skip Whh load entirely.
// prek >= 2: A-warp computes Wih0 @ g_anchors[prek] -> pre slot 7+prek.
__device__ void lstm_phase(const __half* __restrict__ Wih,
                           const __half* __restrict__ Whh,
                           const float* __restrict__ bsum,   // [4][H]
                           int xk, const float* __restrict__ xp,
                           bool hz, int prek,
                           const float* __restrict__ hprev,
                           float* __restrict__ cvec,
                           float* __restrict__ hout,
                           float* __restrict__ anchor_dst,
                           float4* sEx, float4* sOx, float4* sEh, float4* sOh,
                           float (*sA)[4], float (*sB)[4]) {
    int tid = threadIdx.x, w = tid >> 5, lane = tid & 31;
    bool isA = (w < WPB);
    int elem = isA ? w : (w - WPB);
    int gw = blockIdx.x * WPB + elem;
    bool valid = (gw < H);

    if (xk == -1) {
        const float4* x4 = (const float4*)xp;
        for (int i = tid; i < 256; i += NT) {
            sEx[i] = __ldcg(x4 + 2 * i);
            sOx[i] = __ldcg(x4 + 2 * i + 1);
        }
    } else if (prek >= 2) {
        const float4* a4 = (const float4*)g_anchors[prek];
        for (int i = tid; i < 256; i += NT) {
            sEx[i] = __ldcg(a4 + 2 * i);
            sOx[i] = __ldcg(a4 + 2 * i + 1);
        }
    }
    if (!hz) {
        const float4* h4 = (const float4*)hprev;
        for (int i = tid; i < 256; i += NT) {
            sEh[i] = __ldcg(h4 + 2 * i);
            sOh[i] = __ldcg(h4 + 2 * i + 1);
        }
    }
    __syncthreads();

    if (valid) {
        float r[4] = {0.0f, 0.0f, 0.0f, 0.0f};
        if (isA) {
            if (xk == -1) {
#pragma unroll
                for (int g = 0; g < 4; g++)
                    r[g] = dotrow((const uint4*)(Wih + ((size_t)g * H + gw) * H), sEx, sOx, lane);
            } else if (prek >= 2) {
                // anchor-pre pass: Wih0 stream, evict-first to protect L2 hot set
#pragma unroll
                for (int g = 0; g < 4; g++) {
                    float a = dotrow_lu((const uint4*)(Wih + ((size_t)g * H + gw) * H), sEx, sOx, lane);
                    a = warp_reduce(a);
                    if (lane == 0) g_pre[7 + prek][g][gw] = a;
                }
            } else if (!hz) {
                // lookup-x phase: A takes Whh gates 0-1
#pragma unroll
                for (int g = 0; g < 2; g++)
                    r[g] = dotrow((const uint4*)(Whh + ((size_t)g * H + gw) * H), sEh, sOh, lane);
            }
        } else {
            if (!hz) {
                if (xk == -1 || prek >= 2) {
#pragma unroll
                    for (int g = 0; g < 4; g++)
                        r[g] = dotrow((const uint4*)(Whh + ((size_t)g * H + gw) * H), sEh, sOh, lane);
                } else {
                    // lookup-x phase: B takes Whh gates 2-3
#pragma unroll
                    for (int g = 2; g < 4; g++)
                        r[g] = dotrow((const uint4*)(Whh + ((size_t)g * H + gw) * H), sEh, sOh, lane);
                }
            }
        }
#pragma unroll
        for (int g = 0; g < 4; g++) r[g] = warp_reduce(r[g]);
        if (lane == 0) {
            float (*dst)[4] = isA ? sA : sB;
            dst[elem][0] = r[0]; dst[elem][1] = r[1];
            dst[elem][2] = r[2]; dst[elem][3] = r[3];
        }
    }
    __syncthreads();

    if (valid && isA && lane == 0) {
        float g4[4];
#pragma unroll
        for (int g = 0; g < 4; g++)
            g4[g] = sA[elem][g] + sB[elem][g]
                  + (xk >= 0 ? __ldcg(&g_pre[xk][g][gw]) : 0.0f)
                  + bsum[g * H + gw];
        float c2 = sigf(g4[1]) * cvec[gw] + sigf(g4[0]) * tanhf(g4[2]);
        float h2 = sigf(g4[3]) * tanhf(c2);
        cvec[gw] = c2;
        hout[gw] = h2;
        if (anchor_dst) anchor_dst[gw] = h2;
    }
}

// ---------------- matvec phase: dst[gw] = dot(M[gw,:], v); split row halves ----
__device__ void matvec_phase(const __half* __restrict__ M,
                             const float* __restrict__ v,
                             float* __restrict__ dst,
                             float4* sEh, float4* sOh,
                             float (*sA)[4], float (*sB)[4]) {
    int tid = threadIdx.x, w = tid >> 5, lane = tid & 31;
    bool isA = (w < WPB);
    int elem = isA ? w : (w - WPB);
    int gw = blockIdx.x * WPB + elem;
    bool valid = (gw < H);

    const float4* h4 = (const float4*)v;
    for (int i = tid; i < 256; i += NT) {
        sEh[i] = __ldcg(h4 + 2 * i);
        sOh[i] = __ldcg(h4 + 2 * i + 1);
    }
    __syncthreads();

    if (valid) {
        const uint4* row = (const uint4*)(M + (size_t)gw * H);
        int off = isA ? 0 : 4;
        uint4 q[4];
#pragma unroll
        for (int i = 0; i < 4; i++) q[i] = __ldcg(row + (off + i) * 32 + lane);
        float acc = 0.0f;
#pragma unroll
        for (int i = 0; i < 4; i++) {
            int m = (off + i) * 32 + lane;
            acc += dot8(q[i], sEh[m], sOh[m]);
        }
        acc = warp_reduce(acc);
        if (lane == 0) (isA ? sA : sB)[elem][0] = acc;
    }
    __syncthreads();
    if (valid && isA && lane == 0) dst[gw] = sA[elem][0] + sB[elem][0];
}

// ---------------- sampling (R7-proven, redundant across ALL blocks) ----------
__device__ int node_sample(const float* __restrict__ v_attn, int n, int t, int slot,
                           float* s_log, int* s_sel, float* s_stats, int* s_arc) {
    int tid = threadIdx.x, w = tid >> 5, lane = tid & 31;
    if (w < n) {
        const float4* aw = (const float4*)g_anchors_w1[w];
        const float4* hw4 = (const float4*)g_hw;
        const float4* va = (const float4*)v_attn;
        float acc = 0.0f;
#pragma unroll 4
        for (int i = lane; i < H / 4; i += 32) {
            float4 a = __ldcg(aw + i), b = __ldcg(hw4 + i), c = __ldg(va + i);
            acc += c.x * tanhf(a.x + b.x) + c.y * tanhf(a.y + b.y)
                 + c.z * tanhf(a.z + b.z) + c.w * tanhf(a.w + b.w);
        }
        acc = warp_reduce(acc);
        if (lane == 0) s_log[w] = acc;
    }
    __syncthreads();
    if (w == 0) {
        float lv = (lane < n) ? 2.5f * tanhf(s_log[lane] / 5.0f) : -1e30f;
        int bi = sample_warp(lv, n, t, slot, s_stats, s_arc);
        if (lane == 0) *s_sel = bi;
    }
    __syncthreads();
    return *s_sel;
}

__device__ int op_sample(const float* __restrict__ w_soft_w,
                         const float* __restrict__ w_soft_b,
                         const float* __restrict__ h1,
                         int t, int slot,
                         float* s_log, int* s_sel, float* s_stats, int* s_arc) {
    int tid = threadIdx.x, w = tid >> 5, lane = tid & 31;
    if (w < NOPS) {
        const float4* row = (const float4*)(w_soft_w + (size_t)w * H);
        const float4* h4 = (const float4*)h1;
        float acc = 0.0f;
#pragma unroll 4
        for (int i = lane; i < H / 4; i += 32) {
            float4 a = __ldg(row + i), b = __ldcg(h4 + i);
            acc += a.x * b.x + a.y * b.y + a.z * b.z + a.w * b.w;
        }
        acc = warp_reduce(acc);
        if (lane == 0) s_log[w] = acc + __ldg(w_soft_b + w);
    }
    __syncthreads();
    if (w == 0) {
        float lv = (lane < NOPS) ? tanhf(s_log[lane] / 5.0f) : -1e30f;  // TANH_C/OP_TANH_RED = 1
        int bi = sample_warp(lv, NOPS, t, slot, s_stats, s_arc);
        if (lane == 0) *s_sel = bi;
    }
    __syncthreads();
    return *s_sel;
}

// ---------------- the persistent kernel ----------------
__global__ void __launch_bounds__(NT, 1) controller_kernel(
    const float* __restrict__ w_emb, const float* __restrict__ emb_attn,
    const float* __restrict__ hid_attn, const float* __restrict__ v_attn,
    const float* __restrict__ w_soft_w, const float* __restrict__ w_soft_b,
    const float* __restrict__ w_ih, const float* __restrict__ w_hh,
    const float* __restrict__ b_ih, const float* __restrict__ b_hh,
    float* __restrict__ out) {
    __shared__ float4 sEx[256], sOx[256], sEh[256], sOh[256];
    __shared__ float sA[WPB][4], sB[WPB][4];
    __shared__ float s_log[NOPS];
    __shared__ int s_sel;
    __shared__ float s_stats[2];
    __shared__ int s_arc[4 * NNODES];

    // phase 0: fp16 staging + state init + combined biases
    conv_arr(w_ih, g_wih_h, 2 * 4 * H * H / 8);
    conv_arr(w_hh, g_whh_h, 2 * 4 * H * H / 8);
    conv_arr(emb_attn, g_emba_h, H * H / 8);
    conv_arr(hid_attn, g_hida_h, H * H / 8);
    {
        int gid = blockIdx.x * NT + threadIdx.x;
        if (gid < (NNODES + 2) * H) ((float*)g_anchors)[gid] = 0.0f;
        if (gid < 2 * H) ((float*)g_c)[gid] = 0.0f;
        if (gid < 2 * H) ((float*)g_h0)[gid] = 0.0f;
        if (gid < 2 * H) ((float*)g_h1)[gid] = 0.0f;
        if (gid < 2 * 4 * H) ((float*)g_bsum)[gid] = b_ih[gid] + b_hh[gid];
        if (threadIdx.x == 0) { s_stats[0] = 0.0f; s_stats[1] = 0.0f; }
    }
    grid_sync();

    // phase 1: Wih0 @ all-9-embeddings precompute (warp-pair split)
    precompute_phase(g_wih_h, w_emb);
    grid_sync();

    const __half* Wih0 = g_wih_h;
    const __half* Wih1 = g_wih_h + (size_t)4 * H * H;
    const __half* Whh0 = g_whh_h;
    const __half* Whh1 = g_whh_h + (size_t)4 * H * H;
    const float* bs0 = &g_bsum[0][0][0];
    const float* bs1 = &g_bsum[1][0][0];

    int cur = 0;
    int xk = NOPS;                 // start input: g-embedding (w_emb row 8)
    int prek = -1;
    bool hz = true;                // step 1: all h/c are zero -> skip Whh loads

#define STEP(ANCH) do {                                                       \
    lstm_phase(Wih0, Whh0, bs0, xk, nullptr, hz, prek, g_h0[cur], g_c[0],     \
               g_h0[cur ^ 1], nullptr, sEx, sOx, sEh, sOh, sA, sB);           \
    grid_sync();                                                              \
    lstm_phase(Wih1, Whh1, bs1, -1, g_h0[cur ^ 1], hz, -1, g_h1[cur],         \
               g_c[1], g_h1[cur ^ 1], (ANCH), sEx, sOx, sEh, sOh, sA, sB);    \
    grid_sync();                                                              \
    cur ^= 1; hz = false; prek = -1;                                          \
} while (0)

    // warm-up: two steps registering zero anchors + attn projections.
    STEP(nullptr);
    matvec_phase(g_emba_h, g_h1[cur], g_anchors_w1[0], sEh, sOh, sA, sB);
    __syncthreads();
    STEP(nullptr);
    matvec_phase(g_emba_h, g_h1[cur], g_anchors_w1[1], sEh, sOh, sA, sB);
    __syncthreads();

    int t = 0;
    for (int nid = 0; nid < NNODES; nid++) {
        // node-decision step 1 (x = g-emb lookup; also precompute the newest
        // anchor's Wih0 projection so node inputs become pure table lookups)
        if (nid >= 1) prek = nid + 1;
        STEP(nullptr);
        matvec_phase(g_hida_h, g_h1[cur], g_hw, sEh, sOh, sA, sB);
        grid_sync();
        int bi = node_sample(v_attn, nid + 2, t, 4 * nid, s_log, &s_sel, s_stats, s_arc);
        t++;
        xk = (bi < 2) ? -2 : (7 + bi);

        // node-decision step 2
        STEP(nullptr);
        matvec_phase(g_hida_h, g_h1[cur], g_hw, sEh, sOh, sA, sB);
        grid_sync();
        bi = node_sample(v_attn, nid + 2, t, 4 * nid + 2, s_log, &s_sel, s_stats, s_arc);
        t++;
        xk = (bi < 2) ? -2 : (7 + bi);

        // op step 1
        STEP(nullptr);
        int oi = op_sample(w_soft_w, w_soft_b, g_h1[cur], t, 4 * nid + 1,
                           s_log, &s_sel, s_stats, s_arc);
        t++;
        xk = oi;

        // op step 2
        STEP(nullptr);
        oi = op_sample(w_soft_w, w_soft_b, g_h1[cur], t, 4 * nid + 3,
                       s_log, &s_sel, s_stats, s_arc);
        t++;
        xk = oi;

        // anchor registration step (last node's anchor never affects outputs)
        if (nid < NNODES - 1) {
            STEP(g_anchors[nid + 2]);
            matvec_phase(g_emba_h, g_h1[cur], g_anchors_w1[nid + 2], sEh, sOh, sA, sB);
            __syncthreads();           // block-local; consumed >=2 barriers later
            xk = NOPS;
        }
    }
#undef STEP

    if (blockIdx.x == 0) {
        int i = threadIdx.x;
        if (i < 28) out[i] = (float)s_arc[i];
        if (i == 28) out[28] = s_stats[0];
        if (i == 29) out[29] = s_stats[1];
    }
}

// ---------------- host driver: ONE persistent kernel launch ----------------
extern "C" void kernel_launch(void* const* d_in, const int* in_sizes, int n_in,
                              void* d_out, int out_size) {
    const float* w_emb    = (const float*)d_in[0];
    const float* emb_attn = (const float*)d_in[1];
    const float* hid_attn = (const float*)d_in[2];
    const float* v_attn   = (const float*)d_in[3];
    const float* w_soft_w = (const float*)d_in[4];
    const float* w_soft_b = (const float*)d_in[5];
    const float* w_ih     = (const float*)d_in[6];
    const float* w_hh     = (const float*)d_in[7];
    const float* b_ih     = (const float*)d_in[8];
    const float* b_hh     = (const float*)d_in[9];

    controller_kernel<<<NB, NT>>>(w_emb, emb_attn, hid_attn, v_attn,
                                  w_soft_w, w_soft_b, w_ih, w_hh, b_ih, b_hh,
                                  (float*)d_out);
}